// round 1
// baseline (speedup 1.0000x reference)
#include <cuda_runtime.h>

#define BATCH   2048
#define FDIM    512
#define NTREES  512
#define TDEPTH  5
#define NLEAF   32
#define NCOLS   (NTREES * TDEPTH)   // 2560

#define BM 128     // batch rows per block
#define TB 32      // trees per block (BN = 160 columns)
#define KT 16      // K chunk
#define TM 8       // rows per thread

// softmaxed feature-attention weights (scratch): [FDIM, NCOLS]
__device__ float g_W[FDIM * NCOLS];

// ---------------------------------------------------------------------------
// Column softmax over feat_attention (axis 0, 512 entries per column).
// Block = 32 columns x 8 row-groups; warp loads 32 consecutive columns
// (fully coalesced, stride NCOLS between rows).
// ---------------------------------------------------------------------------
__global__ void softmax_kernel(const float* __restrict__ fa) {
    const int lx = threadIdx.x & 31;
    const int ry = threadIdx.x >> 5;          // 0..7
    const int c  = blockIdx.x * 32 + lx;

    __shared__ float red[8][32];

    float m = -1e30f;
    for (int f = ry; f < FDIM; f += 8)
        m = fmaxf(m, fa[f * NCOLS + c]);
    red[ry][lx] = m;
    __syncthreads();
    if (ry == 0) {
        float mm = red[0][lx];
        #pragma unroll
        for (int r = 1; r < 8; r++) mm = fmaxf(mm, red[r][lx]);
        red[0][lx] = mm;
    }
    __syncthreads();
    const float mx = red[0][lx];
    __syncthreads();

    float s = 0.f;
    for (int f = ry; f < FDIM; f += 8)
        s += __expf(fa[f * NCOLS + c] - mx);
    red[ry][lx] = s;
    __syncthreads();
    if (ry == 0) {
        float t = 0.f;
        #pragma unroll
        for (int r = 0; r < 8; r++) t += red[r][lx];
        red[0][lx] = t;
    }
    __syncthreads();
    const float inv = 1.0f / red[0][lx];

    for (int f = ry; f < FDIM; f += 8)
        g_W[f * NCOLS + c] = __expf(fa[f * NCOLS + c] - mx) * inv;
}

// ---------------------------------------------------------------------------
// Fused GEMM (feature_values = x @ W) + oblivious-tree routing epilogue.
// Block: 128 batch rows x 32 trees (160 GEMM cols). 256 threads.
// Thread: TM=8 rows x 2 trees (10 cols) register tile.
// Epilogue per (row, tree): 5 temperature-scaled split gates ->
// 32-leaf probability via 5-level doubling -> dot with response.
// ---------------------------------------------------------------------------
__global__ __launch_bounds__(256, 1)
void detree_kernel(const float* __restrict__ x,
                   const float* __restrict__ thr,
                   const float* __restrict__ logt,
                   const float* __restrict__ resp,
                   float* __restrict__ out) {
    __shared__ float Xs[KT][BM];        // 8 KB
    __shared__ float Ws[KT][TB][8];     // 16 KB, depth padded 5->8 for aligned float4

    const int tid   = threadIdx.x;
    const int tx    = tid & 15;         // tree-pair index (2 trees each)
    const int ty    = tid >> 4;         // row-group index
    const int b0    = blockIdx.y * BM;
    const int tree0 = blockIdx.x * TB;
    const int c0    = tree0 * TDEPTH;

    float acc[TM][10];
    #pragma unroll
    for (int i = 0; i < TM; i++)
        #pragma unroll
        for (int j = 0; j < 10; j++) acc[i][j] = 0.f;

    for (int k0 = 0; k0 < FDIM; k0 += KT) {
        // X tile: 128 x 16, loaded as float4 per thread (2 each)
        #pragma unroll
        for (int r = 0; r < 2; r++) {
            int idx = tid + r * 256;
            int m = idx >> 2, kq = idx & 3;
            float4 v = *(const float4*)&x[(size_t)(b0 + m) * FDIM + k0 + kq * 4];
            Xs[kq * 4 + 0][m] = v.x;
            Xs[kq * 4 + 1][m] = v.y;
            Xs[kq * 4 + 2][m] = v.z;
            Xs[kq * 4 + 3][m] = v.w;
        }
        // W tile: 16 x 160 (coalesced in column index), scattered into padded layout
        #pragma unroll
        for (int r = 0; r < 10; r++) {
            int idx = tid + r * 256;
            int k = idx / 160, cc = idx - k * 160;
            Ws[k][cc / 5][cc % 5] = g_W[(size_t)(k0 + k) * NCOLS + c0 + cc];
        }
        __syncthreads();

        #pragma unroll
        for (int k = 0; k < KT; k++) {
            float4 xa = *(const float4*)&Xs[k][ty * TM];
            float4 xb = *(const float4*)&Xs[k][ty * TM + 4];
            float xr[TM] = {xa.x, xa.y, xa.z, xa.w, xb.x, xb.y, xb.z, xb.w};
            #pragma unroll
            for (int t = 0; t < 2; t++) {
                const int tr = tx * 2 + t;
                float4 w0 = *(const float4*)&Ws[k][tr][0];
                float  w4 = Ws[k][tr][4];
                float wv[5] = {w0.x, w0.y, w0.z, w0.w, w4};
                #pragma unroll
                for (int i = 0; i < TM; i++)
                    #pragma unroll
                    for (int d = 0; d < 5; d++)
                        acc[i][t * 5 + d] = fmaf(xr[i], wv[d], acc[i][t * 5 + d]);
            }
        }
        __syncthreads();
    }

    // ---- epilogue: reuse Xs smem (2048 floats) ----
    // layout: [0..1023] response (32 trees x 32 leaves),
    //         [1024..1183] thresholds, [1184..1343] exp(-log_temperature)
    float* sm = &Xs[0][0];
    #pragma unroll
    for (int r = 0; r < 4; r++) {
        int idx = tid + r * 256;
        sm[idx] = resp[tree0 * NLEAF + idx];   // response is [tree][1][32] contiguous
    }
    if (tid < TB * TDEPTH) {
        sm[1024 + tid] = thr[tree0 * TDEPTH + tid];
        sm[1184 + tid] = __expf(-logt[tree0 * TDEPTH + tid]);
    }
    __syncthreads();

    #pragma unroll
    for (int t = 0; t < 2; t++) {
        const int lt = tx * 2 + t;
        const int n  = tree0 + lt;
        float th[5], it[5];
        #pragma unroll
        for (int d = 0; d < 5; d++) {
            th[d] = sm[1024 + lt * TDEPTH + d];
            it[d] = sm[1184 + lt * TDEPTH + d];
        }
        const float4* r4 = (const float4*)&sm[lt * NLEAF];

        #pragma unroll
        for (int i = 0; i < TM; i++) {
            float c0a[5], c1a[5];
            #pragma unroll
            for (int d = 0; d < 5; d++) {
                float tl = (acc[i][t * 5 + d] - th[d]) * it[d];
                c1a[d] = __saturatef(fmaf( 0.5f, tl, 0.5f));   // clip(0.5*tl+0.5)
                c0a[d] = __saturatef(fmaf(-0.5f, tl, 0.5f));   // clip(-0.5*tl+0.5)
            }
            // leaf-probability tensor-product expansion: p[leaf], bit j of leaf
            // selects c1a[j] (set) or c0a[j] (clear)
            float p[NLEAF];
            p[0] = c0a[0];
            p[1] = c1a[0];
            #pragma unroll
            for (int j = 1; j < TDEPTH; j++) {
                const int sz = 1 << j;
                #pragma unroll
                for (int l = 0; l < 16; l++) {
                    if (l < sz) {
                        p[l + sz] = p[l] * c1a[j];
                        p[l]      = p[l] * c0a[j];
                    }
                }
            }
            float s = 0.f;
            #pragma unroll
            for (int q = 0; q < 8; q++) {
                float4 rv = r4[q];
                s = fmaf(p[4 * q + 0], rv.x, s);
                s = fmaf(p[4 * q + 1], rv.y, s);
                s = fmaf(p[4 * q + 2], rv.z, s);
                s = fmaf(p[4 * q + 3], rv.w, s);
            }
            out[(size_t)(b0 + ty * TM + i) * NTREES + n] = s;
        }
    }
}

extern "C" void kernel_launch(void* const* d_in, const int* in_sizes, int n_in,
                              void* d_out, int out_size) {
    const float* x    = (const float*)d_in[0];
    const float* fa   = (const float*)d_in[1];
    const float* thr  = (const float*)d_in[2];
    const float* logt = (const float*)d_in[3];
    const float* resp = (const float*)d_in[4];
    // d_in[5] = path_map: fixed oblivious mapping, hardcoded in the epilogue.
    float* out = (float*)d_out;

    softmax_kernel<<<NCOLS / 32, 256>>>(fa);
    detree_kernel<<<dim3(NTREES / TB, BATCH / BM), 256>>>(x, thr, logt, resp, out);
}

// round 3
// speedup vs baseline: 3.8890x; 3.8890x over previous
#include <cuda_runtime.h>
#include <cstdint>

#define BATCH   2048
#define FDIM    512
#define NTREES  512
#define NCOLS   2560
#define TDEPTH  5
#define NLEAF   32

#define BM      128      // batch rows per CTA
#define TB      32       // trees per CTA
#define BN      160      // GEMM N per CTA
#define KC      32       // K per chunk
#define NCHUNK  16       // 512/32

// W transposed + softmaxed: [NCOLS][FDIM], K-major per column (scratch)
__device__ float g_Wt[NCOLS * FDIM];

// smem map (bytes). Stages: A 128x32 f32 = 16KB, B 160x32 f32 = 20KB.
#define OFF_A0   0
#define OFF_B0   16384
#define OFF_A1   36864
#define OFF_B1   53248
// epilogue D tile reuses [0, 82944): 128 x 162 floats
#define OFF_RESP 82944
#define OFF_THR  87040
#define OFF_IT   87680
#define SMEM_BYTES 88320

__device__ __forceinline__ uint32_t f2tf32(float f) {
    uint32_t u;
    asm("cvt.rna.tf32.f32 %0, %1;" : "=r"(u) : "f"(f));
    return u;
}

// mma.sync m16n8k8 tf32: A={a0,a1,a2,a3}, B={b0,b1}
// aLo=(a0,a2) row g cols (tig,tig+4); aHi=(a1,a3) row g+8; b=(b0,b1) rows tig,tig+4
__device__ __forceinline__ void mma8(float* d, uint2 aLo, uint2 aHi, uint2 b) {
    asm volatile(
        "mma.sync.aligned.m16n8k8.row.col.f32.tf32.tf32.f32 "
        "{%0,%1,%2,%3}, {%4,%5,%6,%7}, {%8,%9}, {%0,%1,%2,%3};"
        : "+f"(d[0]), "+f"(d[1]), "+f"(d[2]), "+f"(d[3])
        : "r"(aLo.x), "r"(aHi.x), "r"(aLo.y), "r"(aHi.y), "r"(b.x), "r"(b.y));
}

// ---------------------------------------------------------------------------
// Softmax over feat_attention axis 0 -> transposed g_Wt[n][f]
// ---------------------------------------------------------------------------
__global__ void softmax_t_kernel(const float* __restrict__ fa) {
    const int lx = threadIdx.x & 31;
    const int ry = threadIdx.x >> 5;
    const int c0 = blockIdx.x * 32;
    const int c  = c0 + lx;

    __shared__ float red[8][32];
    __shared__ float s_mx[32], s_inv[32];
    __shared__ float tile[32][33];

    float m = -1e30f;
    for (int f = ry; f < FDIM; f += 8) m = fmaxf(m, fa[f * NCOLS + c]);
    red[ry][lx] = m;
    __syncthreads();
    if (ry == 0) {
        float mm = red[0][lx];
        #pragma unroll
        for (int r = 1; r < 8; r++) mm = fmaxf(mm, red[r][lx]);
        s_mx[lx] = mm;
    }
    __syncthreads();
    const float mx = s_mx[lx];

    float s = 0.f;
    for (int f = ry; f < FDIM; f += 8) s += __expf(fa[f * NCOLS + c] - mx);
    red[ry][lx] = s;
    __syncthreads();
    if (ry == 0) {
        float t = 0.f;
        #pragma unroll
        for (int r = 0; r < 8; r++) t += red[r][lx];
        s_inv[lx] = 1.0f / t;
    }
    __syncthreads();
    const float inv = s_inv[lx];

    const int n_local = threadIdx.x >> 3;
    const int fq      = threadIdx.x & 7;

    for (int f0 = 0; f0 < FDIM; f0 += 32) {
        #pragma unroll
        for (int j = 0; j < 4; j++) {
            int fl = ry + j * 8;
            tile[fl][lx] = __expf(fa[(f0 + fl) * NCOLS + c] - mx) * inv;
        }
        __syncthreads();
        float4 v;
        v.x = tile[fq * 4 + 0][n_local];
        v.y = tile[fq * 4 + 1][n_local];
        v.z = tile[fq * 4 + 2][n_local];
        v.w = tile[fq * 4 + 3][n_local];
        *(float4*)&g_Wt[(size_t)(c0 + n_local) * FDIM + f0 + fq * 4] = v;
        __syncthreads();
    }
}

// ---------------------------------------------------------------------------
// Main: tf32 mma.sync GEMM (128x160x512) + fused tree-routing epilogue.
// Smem operand layout per row: 16 float2, pair j=(s*4+p) holds k = s*8+p and
// s*8+p+4, stored at float2 index ((s*4+4*(row&3))&15)+p  (rotation -> 2-phase
// LDS.64 fragment loads, conflict-light STS.128 stores).
// ---------------------------------------------------------------------------
__global__ __launch_bounds__(256, 1)
void detree_mma_kernel(const float* __restrict__ x,
                       const float* __restrict__ thr,
                       const float* __restrict__ logt,
                       const float* __restrict__ resp,
                       float* __restrict__ out) {
    extern __shared__ char sm[];
    float* s_resp = (float*)(sm + OFF_RESP);
    float* s_thr  = (float*)(sm + OFF_THR);
    float* s_it   = (float*)(sm + OFF_IT);
    float* s_D    = (float*)sm;

    const int tid  = threadIdx.x;
    const int wid  = tid >> 5;
    const int lane = tid & 31;
    const int g    = lane >> 2;       // group 0..7
    const int tig  = lane & 3;        // thread-in-group
    const int wm   = wid >> 2;        // warp m index (0..1)
    const int wn   = wid & 3;         // warp n index (0..3)
    const int m0    = blockIdx.y * BM;
    const int tree0 = blockIdx.x * TB;
    const int n0    = tree0 * TDEPTH;

    // epilogue tables
    ((float4*)s_resp)[tid] = ((const float4*)(resp + (size_t)tree0 * NLEAF))[tid];
    if (tid < TB * TDEPTH) {
        s_thr[tid] = thr[n0 + tid];
        s_it[tid]  = __expf(-logt[n0 + tid]);
    }

    // loader cell mapping: cell -> (row = cell>>2, s = cell&3); cell covers 8 k
    const int rA0 = tid >> 2,        sA0 = tid & 3;
    const int rA1 = rA0 + 64;        // cell tid+256
    const int cB2 = 512 + tid;
    const int rB0 = tid >> 2,        sB0 = tid & 3;
    const int rB1 = rB0 + 64;
    const int rB2 = cB2 >> 2,        sB2 = cB2 & 3;
    const bool hasB2 = (tid < 128);

    float4 aLo[2], aHi[2], bLo[3], bHi[3];

    auto ldg_chunk = [&](int k0) {
        const float* xa = x + (size_t)m0 * FDIM + k0;
        const float* wb = g_Wt + (size_t)n0 * FDIM + k0;
        aLo[0] = *(const float4*)(xa + (size_t)rA0 * FDIM + sA0 * 8);
        aHi[0] = *(const float4*)(xa + (size_t)rA0 * FDIM + sA0 * 8 + 4);
        aLo[1] = *(const float4*)(xa + (size_t)rA1 * FDIM + sA0 * 8);
        aHi[1] = *(const float4*)(xa + (size_t)rA1 * FDIM + sA0 * 8 + 4);
        bLo[0] = *(const float4*)(wb + (size_t)rB0 * FDIM + sB0 * 8);
        bHi[0] = *(const float4*)(wb + (size_t)rB0 * FDIM + sB0 * 8 + 4);
        bLo[1] = *(const float4*)(wb + (size_t)rB1 * FDIM + sB0 * 8);
        bHi[1] = *(const float4*)(wb + (size_t)rB1 * FDIM + sB0 * 8 + 4);
        if (hasB2) {
            bLo[2] = *(const float4*)(wb + (size_t)rB2 * FDIM + sB2 * 8);
            bHi[2] = *(const float4*)(wb + (size_t)rB2 * FDIM + sB2 * 8 + 4);
        }
    };

    auto sts_cell = [&](uint32_t* base, int r, int s, const float4& lo, const float4& hi) {
        int fb = (s * 4 + 4 * (r & 3)) & 15;              // float2 base index
        uint32_t* p = base + r * 32 + fb * 2;
        *(uint4*)p       = make_uint4(f2tf32(lo.x), f2tf32(hi.x), f2tf32(lo.y), f2tf32(hi.y));
        *(uint4*)(p + 4) = make_uint4(f2tf32(lo.z), f2tf32(hi.z), f2tf32(lo.w), f2tf32(hi.w));
    };

    auto sts_chunk = [&](int st) {
        uint32_t* As = (uint32_t*)(sm + (st ? OFF_A1 : OFF_A0));
        uint32_t* Bs = (uint32_t*)(sm + (st ? OFF_B1 : OFF_B0));
        sts_cell(As, rA0, sA0, aLo[0], aHi[0]);
        sts_cell(As, rA1, sA0, aLo[1], aHi[1]);
        sts_cell(Bs, rB0, sB0, bLo[0], bHi[0]);
        sts_cell(Bs, rB1, sB0, bLo[1], bHi[1]);
        if (hasB2) sts_cell(Bs, rB2, sB2, bLo[2], bHi[2]);
    };

    float d[4][5][4];
    #pragma unroll
    for (int mt = 0; mt < 4; mt++)
        #pragma unroll
        for (int nt = 0; nt < 5; nt++)
            #pragma unroll
            for (int q = 0; q < 4; q++) d[mt][nt][q] = 0.f;

    // prologue
    ldg_chunk(0);
    sts_chunk(0);
    if (NCHUNK > 1) ldg_chunk(KC);
    __syncthreads();

    for (int i = 0; i < NCHUNK; i++) {
        const int st = i & 1;
        if (i + 1 < NCHUNK) sts_chunk(st ^ 1);
        if (i + 2 < NCHUNK) ldg_chunk((i + 2) * KC);

        const uint32_t* As = (const uint32_t*)(sm + (st ? OFF_A1 : OFF_A0));
        const uint32_t* Bs = (const uint32_t*)(sm + (st ? OFF_B1 : OFF_B0));

        #pragma unroll
        for (int s = 0; s < 4; s++) {
            const int fb = ((s * 4 + tig) + 4 * (g & 3)) & 15;
            uint2 afLo[4], afHi[4], bf[5];
            #pragma unroll
            for (int mt = 0; mt < 4; mt++) {
                int row = wm * 64 + mt * 16 + g;
                afLo[mt] = *((const uint2*)(As + row * 32) + fb);
                afHi[mt] = *((const uint2*)(As + (row + 8) * 32) + fb);
            }
            #pragma unroll
            for (int nt = 0; nt < 5; nt++) {
                int row = wn * 40 + nt * 8 + g;
                bf[nt] = *((const uint2*)(Bs + row * 32) + fb);
            }
            #pragma unroll
            for (int mt = 0; mt < 4; mt++)
                #pragma unroll
                for (int nt = 0; nt < 5; nt++)
                    mma8(d[mt][nt], afLo[mt], afHi[mt], bf[nt]);
        }
        __syncthreads();
    }

    // ---- write D to padded smem [128][162] ----
    #pragma unroll
    for (int mt = 0; mt < 4; mt++) {
        const int row0 = wm * 64 + mt * 16 + g;
        #pragma unroll
        for (int nt = 0; nt < 5; nt++) {
            const int col = wn * 40 + nt * 8 + 2 * tig;
            *(float2*)&s_D[row0 * 162 + col]       = make_float2(d[mt][nt][0], d[mt][nt][1]);
            *(float2*)&s_D[(row0 + 8) * 162 + col] = make_float2(d[mt][nt][2], d[mt][nt][3]);
        }
    }
    __syncthreads();

    // ---- tree routing epilogue: 16 (row,tree) pairs per thread ----
    #pragma unroll
    for (int t = 0; t < 16; t++) {
        const int q   = tid + t * 256;
        const int row = q >> 5;
        const int tr  = q & 31;

        float c0a[5], c1a[5];
        #pragma unroll
        for (int dd = 0; dd < TDEPTH; dd++) {
            float fv = s_D[row * 162 + tr * 5 + dd];
            float tl = (fv - s_thr[tr * 5 + dd]) * s_it[tr * 5 + dd];
            c1a[dd] = __saturatef(fmaf( 0.5f, tl, 0.5f));
            c0a[dd] = __saturatef(fmaf(-0.5f, tl, 0.5f));
        }
        float p[NLEAF];
        p[0] = c0a[0];
        p[1] = c1a[0];
        #pragma unroll
        for (int jj = 1; jj < TDEPTH; jj++) {
            const int sz = 1 << jj;
            #pragma unroll
            for (int l = 0; l < 16; l++) {
                if (l < sz) {
                    p[l + sz] = p[l] * c1a[jj];
                    p[l]      = p[l] * c0a[jj];
                }
            }
        }
        float ssum = 0.f;
        const float4* r4 = (const float4*)&s_resp[tr * NLEAF];
        #pragma unroll
        for (int qq = 0; qq < 8; qq++) {
            float4 rv = r4[qq];
            ssum = fmaf(p[4 * qq + 0], rv.x, ssum);
            ssum = fmaf(p[4 * qq + 1], rv.y, ssum);
            ssum = fmaf(p[4 * qq + 2], rv.z, ssum);
            ssum = fmaf(p[4 * qq + 3], rv.w, ssum);
        }
        out[(size_t)(m0 + row) * NTREES + tree0 + tr] = ssum;
    }
}

extern "C" void kernel_launch(void* const* d_in, const int* in_sizes, int n_in,
                              void* d_out, int out_size) {
    const float* x    = (const float*)d_in[0];
    const float* fa   = (const float*)d_in[1];
    const float* thr  = (const float*)d_in[2];
    const float* logt = (const float*)d_in[3];
    const float* resp = (const float*)d_in[4];
    float* out = (float*)d_out;

    cudaFuncSetAttribute(detree_mma_kernel,
                         cudaFuncAttributeMaxDynamicSharedMemorySize, SMEM_BYTES);

    softmax_t_kernel<<<NCOLS / 32, 256>>>(fa);
    detree_mma_kernel<<<dim3(NTREES / TB, BATCH / BM), 256, SMEM_BYTES>>>(
        x, thr, logt, resp, out);
}